// round 2
// baseline (speedup 1.0000x reference)
#include <cuda_runtime.h>
#include <math.h>

#define BB   32
#define SEQ  197
#define DIM  768
#define NHD  12
#define HD   64
#define NL   12
#define NCLS 1000
#define MLPD 3072
#define NTOK (BB*SEQ)     // 6304
#define NPAT 196
#define MT   ((NTOK+63)/64)   // 99 M-tiles

// -------------------- scratch (device globals; no allocation allowed) -----
__device__ float g_X[NTOK*DIM];
__device__ float g_H[NTOK*DIM];
__device__ float g_A[BB*NPAT*DIM];
__device__ float g_Q[NTOK*DIM];
__device__ float g_K[NTOK*DIM];
__device__ float g_V[NTOK*DIM];
__device__ float g_U[(size_t)NTOK*MLPD];

// -------------------- patchify: (B,C,224,224) -> (B*196, 768) ------------
__global__ void patchify_kernel(const float* __restrict__ img)
{
    int idx = blockIdx.x*256 + threadIdx.x;
    const int total = BB*NPAT*DIM;
    if (idx >= total) return;
    int f = idx % DIM;
    int p = (idx / DIM) % NPAT;
    int b = idx / (DIM*NPAT);
    int c = f >> 8;            // f / 256
    int rem = f & 255;
    int i = rem >> 4;
    int j = rem & 15;
    int pr = p / 14, pc = p % 14;
    g_A[idx] = img[(((size_t)b*3 + c)*224 + (pr*16+i))*224 + (pc*16+j)];
}

// -------------------- assemble tokens: cls + embed + pos -> X ------------
__global__ void assemble_kernel(const float* __restrict__ cls,
                                const float* __restrict__ pos)
{
    int idx = blockIdx.x*256 + threadIdx.x;
    if (idx >= NTOK*DIM) return;
    int d = idx % DIM;
    int s = (idx / DIM) % SEQ;
    int b = idx / (DIM*SEQ);
    float v = (s == 0) ? cls[d] : g_H[((size_t)b*NPAT + (s-1))*DIM + d];
    g_X[idx] = v + pos[s*DIM + d];
}

// -------------------- generic tiled SGEMM body ---------------------------
// C-tile (64x64) at (m0, n0). A: MxK row-major (lda), B: KxN row-major (ldb).
// EPI 0: C = acc + bias ; 1: C = gelu(acc+bias) ; 2: C += acc + bias
template<int EPI>
__device__ __forceinline__ void gemm_tile(
    const float* __restrict__ A, int lda,
    const float* __restrict__ Bm, int ldb,
    const float* __restrict__ bias,
    float* __restrict__ C, int ldc,
    int M, int K, int m0, int n0)
{
    __shared__ float As[64][17];
    __shared__ float Bs[16][65];
    int tid = threadIdx.x;
    int tx = tid & 15, ty = tid >> 4;

    float acc[4][4];
#pragma unroll
    for (int i = 0; i < 4; i++)
#pragma unroll
        for (int j = 0; j < 4; j++) acc[i][j] = 0.f;

    int ka = tid & 15;      // k for A load
    int ma = tid >> 4;      // m base for A load
    int nb = tid & 63;      // n for B load
    int kb = tid >> 6;      // k base for B load

    for (int k0 = 0; k0 < K; k0 += 16) {
#pragma unroll
        for (int r = 0; r < 4; r++) {
            int m  = ma + r*16;
            int gm = m0 + m;
            As[m][ka] = (gm < M) ? A[(size_t)gm*lda + k0 + ka] : 0.f;
        }
#pragma unroll
        for (int r = 0; r < 4; r++) {
            int k = kb + r*4;
            Bs[k][nb] = Bm[(size_t)(k0+k)*ldb + n0 + nb];
        }
        __syncthreads();
#pragma unroll
        for (int k = 0; k < 16; k++) {
            float a[4], bv[4];
#pragma unroll
            for (int i = 0; i < 4; i++) a[i]  = As[ty*4+i][k];
#pragma unroll
            for (int j = 0; j < 4; j++) bv[j] = Bs[k][tx*4+j];
#pragma unroll
            for (int i = 0; i < 4; i++)
#pragma unroll
                for (int j = 0; j < 4; j++)
                    acc[i][j] = fmaf(a[i], bv[j], acc[i][j]);
        }
        __syncthreads();
    }

#pragma unroll
    for (int i = 0; i < 4; i++) {
        int gm = m0 + ty*4 + i;
        if (gm >= M) continue;
#pragma unroll
        for (int j = 0; j < 4; j++) {
            int gn = n0 + tx*4 + j;
            float v = acc[i][j] + bias[gn];
            float* cp = &C[(size_t)gm*ldc + gn];
            if (EPI == 1) v = 0.5f*v*(1.f + erff(v*0.70710678118654752f));
            if (EPI == 2) v += *cp;
            *cp = v;
        }
    }
}

template<int EPI>
__global__ __launch_bounds__(256) void gemm_kernel(
    const float* __restrict__ A, int lda,
    const float* __restrict__ Bm, int ldb,
    const float* __restrict__ bias,
    float* __restrict__ C, int ldc, int M, int K)
{
    gemm_tile<EPI>(A, lda, Bm, ldb, bias, C, ldc, M, K,
                   blockIdx.y*64, blockIdx.x*64);
}

// -------------------- per-head QKV projections ---------------------------
// grid: (Mtiles, 12 heads, 3 for q/k/v)
__global__ __launch_bounds__(256) void qkv_kernel(
    const float* __restrict__ Wq, const float* __restrict__ bq,
    const float* __restrict__ Wk, const float* __restrict__ bk,
    const float* __restrict__ Wv, const float* __restrict__ bv,
    int layer)
{
    int h = blockIdx.y, z = blockIdx.z;
    const float* W; const float* bi; float* C;
    if (z == 0)      { W = Wq; bi = bq; C = g_Q; }
    else if (z == 1) { W = Wk; bi = bk; C = g_K; }
    else             { W = Wv; bi = bv; C = g_V; }
    W  += ((size_t)layer*NHD + h)*HD*HD;
    bi += ((size_t)layer*NHD + h)*HD;
    gemm_tile<0>(g_H + h*HD, DIM, W, HD, bi, C + h*HD, DIM,
                 NTOK, HD, blockIdx.x*64, 0);
}

// -------------------- layernorm ------------------------------------------
__global__ __launch_bounds__(256) void ln_kernel(
    const float* __restrict__ X, float* __restrict__ H,
    const float* __restrict__ gw, const float* __restrict__ bw)
{
    __shared__ float rs[8], rq[8];
    int row = blockIdx.x, tid = threadIdx.x;
    int lane = tid & 31, wid = tid >> 5;
    const float* x = X + (size_t)row*DIM;
    float v0 = x[tid], v1 = x[tid+256], v2 = x[tid+512];
    float s = v0+v1+v2;
    float q = v0*v0 + v1*v1 + v2*v2;
#pragma unroll
    for (int o = 16; o; o >>= 1) {
        s += __shfl_xor_sync(0xffffffffu, s, o);
        q += __shfl_xor_sync(0xffffffffu, q, o);
    }
    if (lane == 0) { rs[wid] = s; rq[wid] = q; }
    __syncthreads();
    if (tid == 0) {
        float ts = 0.f, tq = 0.f;
        for (int w = 0; w < 8; w++) { ts += rs[w]; tq += rq[w]; }
        rs[0] = ts; rq[0] = tq;
    }
    __syncthreads();
    float mean = rs[0]*(1.0f/DIM);
    float var  = rq[0]*(1.0f/DIM) - mean*mean;
    float inv  = rsqrtf(var + 1e-5f);
    float* hrow = H + (size_t)row*DIM;
    hrow[tid]     = (v0-mean)*inv*gw[tid]     + bw[tid];
    hrow[tid+256] = (v1-mean)*inv*gw[tid+256] + bw[tid+256];
    hrow[tid+512] = (v2-mean)*inv*gw[tid+512] + bw[tid+512];
}

// -------------------- attention (one block per (b,h)) --------------------
// smem: K tile (197x64), V tile (197x64), q (64), p (197), red (8)
#define ATTN_SMEM_FLOATS (2*SEQ*HD + HD + SEQ + 8)
#define ATTN_SMEM_BYTES  (ATTN_SMEM_FLOATS*4)

__global__ __launch_bounds__(128) void attn_kernel(
    const float* __restrict__ Q, const float* __restrict__ K,
    const float* __restrict__ V, float* __restrict__ X)
{
    extern __shared__ float sm[];
    float* Ks  = sm;
    float* Vs  = Ks + SEQ*HD;
    float* qs  = Vs + SEQ*HD;
    float* ps  = qs + HD;
    float* red = ps + SEQ;

    int bh = blockIdx.x;
    int b = bh / NHD, h = bh % NHD;
    int tid = threadIdx.x;          // 128 threads
    int lane = tid & 31, wid = tid >> 5;
    size_t base = (size_t)b*SEQ*DIM + (size_t)h*HD;

    for (int idx = tid; idx < SEQ*HD; idx += 128) {
        int t = idx >> 6, e = idx & 63;
        Ks[idx] = K[base + (size_t)t*DIM + e];
        Vs[idx] = V[base + (size_t)t*DIM + e];
    }
    __syncthreads();

    int rot = tid & 63;   // rotate inner dim to avoid smem bank conflicts
    for (int s = 0; s < SEQ; s++) {
        if (tid < HD) qs[tid] = Q[base + (size_t)s*DIM + tid];
        __syncthreads();

        float lm = -1e30f;
        for (int j = tid; j < SEQ; j += 128) {
            float d = 0.f;
            const float* kr = &Ks[j*HD];
#pragma unroll
            for (int e = 0; e < HD; e++) {
                int ee = (e + rot) & 63;
                d = fmaf(qs[ee], kr[ee], d);
            }
            d *= 0.125f;            // 1/sqrt(64)
            ps[j] = d;
            lm = fmaxf(lm, d);
        }
#pragma unroll
        for (int o = 16; o; o >>= 1) lm = fmaxf(lm, __shfl_xor_sync(0xffffffffu, lm, o));
        if (lane == 0) red[wid] = lm;
        __syncthreads();
        if (tid == 0) {
            float m = fmaxf(fmaxf(red[0], red[1]), fmaxf(red[2], red[3]));
            red[4] = m;
        }
        __syncthreads();
        float mx = red[4];

        float ls = 0.f;
        for (int j = tid; j < SEQ; j += 128) {
            float e = expf(ps[j] - mx);
            ps[j] = e;
            ls += e;
        }
#pragma unroll
        for (int o = 16; o; o >>= 1) ls += __shfl_xor_sync(0xffffffffu, ls, o);
        __syncthreads();
        if (lane == 0) red[wid] = ls;
        __syncthreads();
        if (tid == 0) red[5] = red[0] + red[1] + red[2] + red[3];
        __syncthreads();
        float inv = 1.f / red[5];

        if (tid < HD) {
            float acc = 0.f;
            for (int t = 0; t < SEQ; t++)
                acc = fmaf(ps[t], Vs[t*HD + tid], acc);
            X[base + (size_t)s*DIM + tid] += acc * inv;   // fused residual add
        }
        __syncthreads();
    }
}

// -------------------- classifier head + softmax --------------------------
__global__ __launch_bounds__(256) void head_kernel(
    const float* __restrict__ X, const float* __restrict__ Wh,
    const float* __restrict__ bh, float* __restrict__ out)
{
    __shared__ float xr[DIM];
    __shared__ float lg[NCLS];
    __shared__ float red[8];
    int b = blockIdx.x, tid = threadIdx.x;
    int lane = tid & 31, wid = tid >> 5;

    for (int d = tid; d < DIM; d += 256) xr[d] = X[(size_t)b*SEQ*DIM + d];
    __syncthreads();

    for (int n = tid; n < NCLS; n += 256) {
        float a = bh[n];
        for (int k = 0; k < DIM; k++)
            a = fmaf(xr[k], Wh[(size_t)k*NCLS + n], a);
        lg[n] = a;
    }
    __syncthreads();

    float lm = -1e30f;
    for (int n = tid; n < NCLS; n += 256) lm = fmaxf(lm, lg[n]);
#pragma unroll
    for (int o = 16; o; o >>= 1) lm = fmaxf(lm, __shfl_xor_sync(0xffffffffu, lm, o));
    if (lane == 0) red[wid] = lm;
    __syncthreads();
    if (tid == 0) {
        float m = red[0];
        for (int w = 1; w < 8; w++) m = fmaxf(m, red[w]);
        red[0] = m;
    }
    __syncthreads();
    float mx = red[0];

    float ls = 0.f;
    for (int n = tid; n < NCLS; n += 256) {
        float e = expf(lg[n] - mx);
        lg[n] = e;
        ls += e;
    }
#pragma unroll
    for (int o = 16; o; o >>= 1) ls += __shfl_xor_sync(0xffffffffu, ls, o);
    __syncthreads();
    if (lane == 0) red[wid] = ls;
    __syncthreads();
    if (tid == 0) {
        float s2 = 0.f;
        for (int w = 0; w < 8; w++) s2 += red[w];
        red[0] = s2;
    }
    __syncthreads();
    float inv = 1.f / red[0];
    for (int n = tid; n < NCLS; n += 256)
        out[(size_t)b*NCLS + n] = lg[n]*inv;
}

// -------------------- launch ---------------------------------------------
extern "C" void kernel_launch(void* const* d_in, const int* in_sizes, int n_in,
                              void* d_out, int out_size)
{
    (void)in_sizes; (void)n_in; (void)out_size;
    const float* images = (const float*)d_in[0];
    const float* Wp     = (const float*)d_in[1];
    const float* bp     = (const float*)d_in[2];
    const float* cls    = (const float*)d_in[3];
    const float* pos    = (const float*)d_in[4];
    const float* ln1_g  = (const float*)d_in[5];
    const float* ln1_b  = (const float*)d_in[6];
    const float* Wq     = (const float*)d_in[7];
    const float* bq     = (const float*)d_in[8];
    const float* Wk     = (const float*)d_in[9];
    const float* bk     = (const float*)d_in[10];
    const float* Wv     = (const float*)d_in[11];
    const float* bv     = (const float*)d_in[12];
    const float* ln2_g  = (const float*)d_in[13];
    const float* ln2_b  = (const float*)d_in[14];
    const float* W1     = (const float*)d_in[15];
    const float* b1     = (const float*)d_in[16];
    const float* W2     = (const float*)d_in[17];
    const float* b2     = (const float*)d_in[18];
    const float* Wh     = (const float*)d_in[19];
    const float* bh     = (const float*)d_in[20];
    float* out = (float*)d_out;

    float *pA, *pH, *pX, *pQ, *pK, *pV, *pU;
    cudaGetSymbolAddress((void**)&pA, g_A);
    cudaGetSymbolAddress((void**)&pH, g_H);
    cudaGetSymbolAddress((void**)&pX, g_X);
    cudaGetSymbolAddress((void**)&pQ, g_Q);
    cudaGetSymbolAddress((void**)&pK, g_K);
    cudaGetSymbolAddress((void**)&pV, g_V);
    cudaGetSymbolAddress((void**)&pU, g_U);

    cudaFuncSetAttribute(attn_kernel,
                         cudaFuncAttributeMaxDynamicSharedMemorySize,
                         ATTN_SMEM_BYTES);

    // Patch embed
    patchify_kernel<<<(BB*NPAT*DIM + 255)/256, 256>>>(images);
    gemm_kernel<0><<<dim3(DIM/64, BB*NPAT/64), 256>>>(
        pA, DIM, Wp, DIM, bp, pH, DIM, BB*NPAT, DIM);
    assemble_kernel<<<(NTOK*DIM + 255)/256, 256>>>(cls, pos);

    for (int l = 0; l < NL; l++) {
        ln_kernel<<<NTOK, 256>>>(pX, pH, ln1_g + l*DIM, ln1_b + l*DIM);
        qkv_kernel<<<dim3(MT, NHD, 3), 256>>>(Wq, bq, Wk, bk, Wv, bv, l);
        attn_kernel<<<BB*NHD, 128, ATTN_SMEM_BYTES>>>(pQ, pK, pV, pX);
        ln_kernel<<<NTOK, 256>>>(pX, pH, ln2_g + l*DIM, ln2_b + l*DIM);
        gemm_kernel<1><<<dim3(MLPD/64, MT), 256>>>(
            pH, DIM, W1 + (size_t)l*DIM*MLPD, MLPD, b1 + (size_t)l*MLPD,
            pU, MLPD, NTOK, DIM);
        gemm_kernel<2><<<dim3(DIM/64, MT), 256>>>(
            pU, MLPD, W2 + (size_t)l*MLPD*DIM, DIM, b2 + (size_t)l*DIM,
            pX, DIM, NTOK, MLPD);
    }

    head_kernel<<<BB, 256>>>(pX, Wh, bh, out);
}

// round 3
// speedup vs baseline: 1.0007x; 1.0007x over previous
#include <cuda_runtime.h>
#include <math.h>

#define BB   32
#define SEQ  197
#define DIM  768
#define NHD  12
#define HD   64
#define NL   12
#define NCLS 1000
#define MLPD 3072
#define NTOK (BB*SEQ)     // 6304
#define NPAT 196
#define MT   ((NTOK+63)/64)   // 99 M-tiles

// -------------------- scratch (device globals; no allocation allowed) -----
__device__ float g_X[NTOK*DIM];
__device__ float g_H[NTOK*DIM];
__device__ float g_A[BB*NPAT*DIM];
__device__ float g_Q[NTOK*DIM];
__device__ float g_K[NTOK*DIM];
__device__ float g_V[NTOK*DIM];
__device__ float g_U[(size_t)NTOK*MLPD];

// -------------------- patchify: (B,C,224,224) -> (B*196, 768) ------------
__global__ void patchify_kernel(const float* __restrict__ img)
{
    int idx = blockIdx.x*256 + threadIdx.x;
    const int total = BB*NPAT*DIM;
    if (idx >= total) return;
    int f = idx % DIM;
    int p = (idx / DIM) % NPAT;
    int b = idx / (DIM*NPAT);
    int c = f >> 8;            // f / 256
    int rem = f & 255;
    int i = rem >> 4;
    int j = rem & 15;
    int pr = p / 14, pc = p % 14;
    g_A[idx] = img[(((size_t)b*3 + c)*224 + (pr*16+i))*224 + (pc*16+j)];
}

// -------------------- assemble tokens: cls + embed + pos -> X ------------
__global__ void assemble_kernel(const float* __restrict__ cls,
                                const float* __restrict__ pos)
{
    int idx = blockIdx.x*256 + threadIdx.x;
    if (idx >= NTOK*DIM) return;
    int d = idx % DIM;
    int s = (idx / DIM) % SEQ;
    int b = idx / (DIM*SEQ);
    float v = (s == 0) ? cls[d] : g_H[((size_t)b*NPAT + (s-1))*DIM + d];
    g_X[idx] = v + pos[s*DIM + d];
}

// -------------------- generic tiled SGEMM body ---------------------------
// C-tile (64x64) at (m0, n0). A: MxK row-major (lda), B: KxN row-major (ldb).
// EPI 0: C = acc + bias ; 1: C = gelu(acc+bias) ; 2: C += acc + bias
template<int EPI>
__device__ __forceinline__ void gemm_tile(
    const float* __restrict__ A, int lda,
    const float* __restrict__ Bm, int ldb,
    const float* __restrict__ bias,
    float* __restrict__ C, int ldc,
    int M, int K, int m0, int n0)
{
    __shared__ float As[64][17];
    __shared__ float Bs[16][65];
    int tid = threadIdx.x;
    int tx = tid & 15, ty = tid >> 4;

    float acc[4][4];
#pragma unroll
    for (int i = 0; i < 4; i++)
#pragma unroll
        for (int j = 0; j < 4; j++) acc[i][j] = 0.f;

    int ka = tid & 15;      // k for A load
    int ma = tid >> 4;      // m base for A load
    int nb = tid & 63;      // n for B load
    int kb = tid >> 6;      // k base for B load

    for (int k0 = 0; k0 < K; k0 += 16) {
#pragma unroll
        for (int r = 0; r < 4; r++) {
            int m  = ma + r*16;
            int gm = m0 + m;
            As[m][ka] = (gm < M) ? A[(size_t)gm*lda + k0 + ka] : 0.f;
        }
#pragma unroll
        for (int r = 0; r < 4; r++) {
            int k = kb + r*4;
            Bs[k][nb] = Bm[(size_t)(k0+k)*ldb + n0 + nb];
        }
        __syncthreads();
#pragma unroll
        for (int k = 0; k < 16; k++) {
            float a[4], bv[4];
#pragma unroll
            for (int i = 0; i < 4; i++) a[i]  = As[ty*4+i][k];
#pragma unroll
            for (int j = 0; j < 4; j++) bv[j] = Bs[k][tx*4+j];
#pragma unroll
            for (int i = 0; i < 4; i++)
#pragma unroll
                for (int j = 0; j < 4; j++)
                    acc[i][j] = fmaf(a[i], bv[j], acc[i][j]);
        }
        __syncthreads();
    }

#pragma unroll
    for (int i = 0; i < 4; i++) {
        int gm = m0 + ty*4 + i;
        if (gm >= M) continue;
#pragma unroll
        for (int j = 0; j < 4; j++) {
            int gn = n0 + tx*4 + j;
            float v = acc[i][j] + bias[gn];
            float* cp = &C[(size_t)gm*ldc + gn];
            if (EPI == 1) v = 0.5f*v*(1.f + erff(v*0.70710678118654752f));
            if (EPI == 2) v += *cp;
            *cp = v;
        }
    }
}

template<int EPI>
__global__ __launch_bounds__(256) void gemm_kernel(
    const float* __restrict__ A, int lda,
    const float* __restrict__ Bm, int ldb,
    const float* __restrict__ bias,
    float* __restrict__ C, int ldc, int M, int K)
{
    gemm_tile<EPI>(A, lda, Bm, ldb, bias, C, ldc, M, K,
                   blockIdx.y*64, blockIdx.x*64);
}

// -------------------- per-head QKV projections ---------------------------
// grid: (Mtiles, 12 heads, 3 for q/k/v)
__global__ __launch_bounds__(256) void qkv_kernel(
    const float* __restrict__ Wq, const float* __restrict__ bq,
    const float* __restrict__ Wk, const float* __restrict__ bk,
    const float* __restrict__ Wv, const float* __restrict__ bv,
    int layer)
{
    int h = blockIdx.y, z = blockIdx.z;
    const float* W; const float* bi; float* C;
    if (z == 0)      { W = Wq; bi = bq; C = g_Q; }
    else if (z == 1) { W = Wk; bi = bk; C = g_K; }
    else             { W = Wv; bi = bv; C = g_V; }
    W  += ((size_t)layer*NHD + h)*HD*HD;
    bi += ((size_t)layer*NHD + h)*HD;
    gemm_tile<0>(g_H + h*HD, DIM, W, HD, bi, C + h*HD, DIM,
                 NTOK, HD, blockIdx.x*64, 0);
}

// -------------------- layernorm ------------------------------------------
__global__ __launch_bounds__(256) void ln_kernel(
    const float* __restrict__ X, float* __restrict__ H,
    const float* __restrict__ gw, const float* __restrict__ bw)
{
    __shared__ float rs[8], rq[8];
    int row = blockIdx.x, tid = threadIdx.x;
    int lane = tid & 31, wid = tid >> 5;
    const float* x = X + (size_t)row*DIM;
    float v0 = x[tid], v1 = x[tid+256], v2 = x[tid+512];
    float s = v0+v1+v2;
    float q = v0*v0 + v1*v1 + v2*v2;
#pragma unroll
    for (int o = 16; o; o >>= 1) {
        s += __shfl_xor_sync(0xffffffffu, s, o);
        q += __shfl_xor_sync(0xffffffffu, q, o);
    }
    if (lane == 0) { rs[wid] = s; rq[wid] = q; }
    __syncthreads();
    if (tid == 0) {
        float ts = 0.f, tq = 0.f;
        for (int w = 0; w < 8; w++) { ts += rs[w]; tq += rq[w]; }
        rs[0] = ts; rq[0] = tq;
    }
    __syncthreads();
    float mean = rs[0]*(1.0f/DIM);
    float var  = rq[0]*(1.0f/DIM) - mean*mean;
    float inv  = rsqrtf(var + 1e-5f);
    float* hrow = H + (size_t)row*DIM;
    hrow[tid]     = (v0-mean)*inv*gw[tid]     + bw[tid];
    hrow[tid+256] = (v1-mean)*inv*gw[tid+256] + bw[tid+256];
    hrow[tid+512] = (v2-mean)*inv*gw[tid+512] + bw[tid+512];
}

// -------------------- attention (one block per (b,h)) --------------------
// smem: K tile (197x64), V tile (197x64), q (64), p (197), red (8)
#define ATTN_SMEM_FLOATS (2*SEQ*HD + HD + SEQ + 8)
#define ATTN_SMEM_BYTES  (ATTN_SMEM_FLOATS*4)

__global__ __launch_bounds__(128) void attn_kernel(
    const float* __restrict__ Q, const float* __restrict__ K,
    const float* __restrict__ V, float* __restrict__ X)
{
    extern __shared__ float sm[];
    float* Ks  = sm;
    float* Vs  = Ks + SEQ*HD;
    float* qs  = Vs + SEQ*HD;
    float* ps  = qs + HD;
    float* red = ps + SEQ;

    int bh = blockIdx.x;
    int b = bh / NHD, h = bh % NHD;
    int tid = threadIdx.x;          // 128 threads
    int lane = tid & 31, wid = tid >> 5;
    size_t base = (size_t)b*SEQ*DIM + (size_t)h*HD;

    for (int idx = tid; idx < SEQ*HD; idx += 128) {
        int t = idx >> 6, e = idx & 63;
        Ks[idx] = K[base + (size_t)t*DIM + e];
        Vs[idx] = V[base + (size_t)t*DIM + e];
    }
    __syncthreads();

    int rot = tid & 63;   // rotate inner dim to avoid smem bank conflicts
    for (int s = 0; s < SEQ; s++) {
        if (tid < HD) qs[tid] = Q[base + (size_t)s*DIM + tid];
        __syncthreads();

        float lm = -1e30f;
        for (int j = tid; j < SEQ; j += 128) {
            float d = 0.f;
            const float* kr = &Ks[j*HD];
#pragma unroll
            for (int e = 0; e < HD; e++) {
                int ee = (e + rot) & 63;
                d = fmaf(qs[ee], kr[ee], d);
            }
            d *= 0.125f;            // 1/sqrt(64)
            ps[j] = d;
            lm = fmaxf(lm, d);
        }
#pragma unroll
        for (int o = 16; o; o >>= 1) lm = fmaxf(lm, __shfl_xor_sync(0xffffffffu, lm, o));
        if (lane == 0) red[wid] = lm;
        __syncthreads();
        if (tid == 0) {
            float m = fmaxf(fmaxf(red[0], red[1]), fmaxf(red[2], red[3]));
            red[4] = m;
        }
        __syncthreads();
        float mx = red[4];

        float ls = 0.f;
        for (int j = tid; j < SEQ; j += 128) {
            float e = expf(ps[j] - mx);
            ps[j] = e;
            ls += e;
        }
#pragma unroll
        for (int o = 16; o; o >>= 1) ls += __shfl_xor_sync(0xffffffffu, ls, o);
        __syncthreads();
        if (lane == 0) red[wid] = ls;
        __syncthreads();
        if (tid == 0) red[5] = red[0] + red[1] + red[2] + red[3];
        __syncthreads();
        float inv = 1.f / red[5];

        if (tid < HD) {
            float acc = 0.f;
            for (int t = 0; t < SEQ; t++)
                acc = fmaf(ps[t], Vs[t*HD + tid], acc);
            X[base + (size_t)s*DIM + tid] += acc * inv;   // fused residual add
        }
        __syncthreads();
    }
}

// -------------------- classifier head + softmax --------------------------
__global__ __launch_bounds__(256) void head_kernel(
    const float* __restrict__ X, const float* __restrict__ Wh,
    const float* __restrict__ bh, float* __restrict__ out)
{
    __shared__ float xr[DIM];
    __shared__ float lg[NCLS];
    __shared__ float red[8];
    int b = blockIdx.x, tid = threadIdx.x;
    int lane = tid & 31, wid = tid >> 5;

    for (int d = tid; d < DIM; d += 256) xr[d] = X[(size_t)b*SEQ*DIM + d];
    __syncthreads();

    for (int n = tid; n < NCLS; n += 256) {
        float a = bh[n];
        for (int k = 0; k < DIM; k++)
            a = fmaf(xr[k], Wh[(size_t)k*NCLS + n], a);
        lg[n] = a;
    }
    __syncthreads();

    float lm = -1e30f;
    for (int n = tid; n < NCLS; n += 256) lm = fmaxf(lm, lg[n]);
#pragma unroll
    for (int o = 16; o; o >>= 1) lm = fmaxf(lm, __shfl_xor_sync(0xffffffffu, lm, o));
    if (lane == 0) red[wid] = lm;
    __syncthreads();
    if (tid == 0) {
        float m = red[0];
        for (int w = 1; w < 8; w++) m = fmaxf(m, red[w]);
        red[0] = m;
    }
    __syncthreads();
    float mx = red[0];

    float ls = 0.f;
    for (int n = tid; n < NCLS; n += 256) {
        float e = expf(lg[n] - mx);
        lg[n] = e;
        ls += e;
    }
#pragma unroll
    for (int o = 16; o; o >>= 1) ls += __shfl_xor_sync(0xffffffffu, ls, o);
    __syncthreads();
    if (lane == 0) red[wid] = ls;
    __syncthreads();
    if (tid == 0) {
        float s2 = 0.f;
        for (int w = 0; w < 8; w++) s2 += red[w];
        red[0] = s2;
    }
    __syncthreads();
    float inv = 1.f / red[0];
    for (int n = tid; n < NCLS; n += 256)
        out[(size_t)b*NCLS + n] = lg[n]*inv;
}

// -------------------- launch ---------------------------------------------
extern "C" void kernel_launch(void* const* d_in, const int* in_sizes, int n_in,
                              void* d_out, int out_size)
{
    (void)in_sizes; (void)n_in; (void)out_size;
    const float* images = (const float*)d_in[0];
    const float* Wp     = (const float*)d_in[1];
    const float* bp     = (const float*)d_in[2];
    const float* cls    = (const float*)d_in[3];
    const float* pos    = (const float*)d_in[4];
    const float* ln1_g  = (const float*)d_in[5];
    const float* ln1_b  = (const float*)d_in[6];
    const float* Wq     = (const float*)d_in[7];
    const float* bq     = (const float*)d_in[8];
    const float* Wk     = (const float*)d_in[9];
    const float* bk     = (const float*)d_in[10];
    const float* Wv     = (const float*)d_in[11];
    const float* bv     = (const float*)d_in[12];
    const float* ln2_g  = (const float*)d_in[13];
    const float* ln2_b  = (const float*)d_in[14];
    const float* W1     = (const float*)d_in[15];
    const float* b1     = (const float*)d_in[16];
    const float* W2     = (const float*)d_in[17];
    const float* b2     = (const float*)d_in[18];
    const float* Wh     = (const float*)d_in[19];
    const float* bh     = (const float*)d_in[20];
    float* out = (float*)d_out;

    float *pA, *pH, *pX, *pQ, *pK, *pV, *pU;
    cudaGetSymbolAddress((void**)&pA, g_A);
    cudaGetSymbolAddress((void**)&pH, g_H);
    cudaGetSymbolAddress((void**)&pX, g_X);
    cudaGetSymbolAddress((void**)&pQ, g_Q);
    cudaGetSymbolAddress((void**)&pK, g_K);
    cudaGetSymbolAddress((void**)&pV, g_V);
    cudaGetSymbolAddress((void**)&pU, g_U);

    cudaFuncSetAttribute(attn_kernel,
                         cudaFuncAttributeMaxDynamicSharedMemorySize,
                         ATTN_SMEM_BYTES);

    // Patch embed
    patchify_kernel<<<(BB*NPAT*DIM + 255)/256, 256>>>(images);
    gemm_kernel<0><<<dim3(DIM/64, BB*NPAT/64), 256>>>(
        pA, DIM, Wp, DIM, bp, pH, DIM, BB*NPAT, DIM);
    assemble_kernel<<<(NTOK*DIM + 255)/256, 256>>>(cls, pos);

    for (int l = 0; l < NL; l++) {
        ln_kernel<<<NTOK, 256>>>(pX, pH, ln1_g + l*DIM, ln1_b + l*DIM);
        qkv_kernel<<<dim3(MT, NHD, 3), 256>>>(Wq, bq, Wk, bk, Wv, bv, l);
        attn_kernel<<<BB*NHD, 128, ATTN_SMEM_BYTES>>>(pQ, pK, pV, pX);
        ln_kernel<<<NTOK, 256>>>(pX, pH, ln2_g + l*DIM, ln2_b + l*DIM);
        gemm_kernel<1><<<dim3(MLPD/64, MT), 256>>>(
            pH, DIM, W1 + (size_t)l*DIM*MLPD, MLPD, b1 + (size_t)l*MLPD,
            pU, MLPD, NTOK, DIM);
        gemm_kernel<2><<<dim3(DIM/64, MT), 256>>>(
            pU, MLPD, W2 + (size_t)l*MLPD*DIM, DIM, b2 + (size_t)l*DIM,
            pX, DIM, NTOK, MLPD);
    }

    head_kernel<<<BB, 256>>>(pX, Wh, bh, out);
}

// round 4
// speedup vs baseline: 1.3609x; 1.3599x over previous
#include <cuda_runtime.h>
#include <math.h>
#include <stdint.h>

#define BB   32
#define SEQ  197
#define DIM  768
#define NHD  12
#define HD   64
#define NL   12
#define NCLS 1000
#define MLPD 3072
#define NTOK (BB*SEQ)     // 6304
#define NPAT 196
#define MT128 ((NTOK+127)/128)   // 50 M-tiles of 128

// -------------------- scratch (device globals; no allocation allowed) -----
__device__ float g_X[NTOK*DIM];
__device__ float g_H[NTOK*DIM];
__device__ float g_A[BB*NPAT*DIM];
__device__ float g_Q[NTOK*DIM];
__device__ float g_K[NTOK*DIM];
__device__ float g_V[NTOK*DIM];
__device__ float g_U[(size_t)NTOK*MLPD];

// -------------------- patchify: (B,C,224,224) -> (B*196, 768) ------------
__global__ void patchify_kernel(const float* __restrict__ img)
{
    int idx = blockIdx.x*256 + threadIdx.x;
    const int total = BB*NPAT*DIM;
    if (idx >= total) return;
    int f = idx % DIM;
    int p = (idx / DIM) % NPAT;
    int b = idx / (DIM*NPAT);
    int c = f >> 8;
    int rem = f & 255;
    int i = rem >> 4;
    int j = rem & 15;
    int pr = p / 14, pc = p % 14;
    g_A[idx] = img[(((size_t)b*3 + c)*224 + (pr*16+i))*224 + (pc*16+j)];
}

// -------------------- assemble tokens: cls + embed + pos -> X ------------
__global__ void assemble_kernel(const float* __restrict__ cls,
                                const float* __restrict__ pos)
{
    int idx = blockIdx.x*256 + threadIdx.x;
    if (idx >= NTOK*DIM) return;
    int d = idx % DIM;
    int s = (idx / DIM) % SEQ;
    int b = idx / (DIM*SEQ);
    float v = (s == 0) ? cls[d] : g_H[((size_t)b*NPAT + (s-1))*DIM + d];
    g_X[idx] = v + pos[s*DIM + d];
}

// ==================== TF32x3 tensor-core GEMM =============================
// C-tile 128x64 per block, 256 threads (8 warps in 4x2), warp tile 32x32.
// A: MxK row-major (lda), B: KxN row-major (ldb).
// Precision: split each operand into tf32 hi + tf32 lo, do hi*hi+hi*lo+lo*hi.
// EPI 0: C = acc + bias ; 1: C = gelu(acc+bias) ; 2: C += acc + bias

#define BM 128
#define BN 64
#define BKK 32

__device__ __forceinline__ void split_tf32(float x, uint32_t& hi, uint32_t& lo)
{
    uint32_t h;
    asm("cvt.rna.tf32.f32 %0, %1;" : "=r"(h) : "f"(x));
    float r = x - __uint_as_float(h);
    uint32_t l;
    asm("cvt.rna.tf32.f32 %0, %1;" : "=r"(l) : "f"(r));
    hi = h; lo = l;
}

__device__ __forceinline__ void mma_tf32(float* cc, const uint32_t* a, const uint32_t* b)
{
    asm volatile(
        "mma.sync.aligned.m16n8k8.row.col.f32.tf32.tf32.f32 "
        "{%0,%1,%2,%3}, {%4,%5,%6,%7}, {%8,%9}, {%0,%1,%2,%3};\n"
        : "+f"(cc[0]), "+f"(cc[1]), "+f"(cc[2]), "+f"(cc[3])
        : "r"(a[0]), "r"(a[1]), "r"(a[2]), "r"(a[3]),
          "r"(b[0]), "r"(b[1]));
}

template<int EPI>
__device__ __forceinline__ void mma_gemm_tile(
    const float* __restrict__ A, int lda,
    const float* __restrict__ Bm, int ldb,
    const float* __restrict__ bias,
    float* __restrict__ C, int ldc,
    int M, int K, int m0, int n0)
{
    __shared__ float As[BM][BKK+4];   // stride 36: frag reads conflict-free
    __shared__ float Bs[BKK][BN+8];   // stride 72: frag reads conflict-free

    int tid  = threadIdx.x;
    int lane = tid & 31, wid = tid >> 5;
    int warpM = wid >> 1, warpN = wid & 1;
    int g = lane >> 2, c = lane & 3;

    float acc[2][4][4];
#pragma unroll
    for (int mt = 0; mt < 2; mt++)
#pragma unroll
        for (int nt = 0; nt < 4; nt++)
#pragma unroll
            for (int i = 0; i < 4; i++) acc[mt][nt][i] = 0.f;

    for (int k0 = 0; k0 < K; k0 += BKK) {
        // load A tile 128x32 (4 float4 / thread)
#pragma unroll
        for (int i = 0; i < 4; i++) {
            int idx = tid + i*256;       // 0..1023
            int row = idx >> 3, c4 = idx & 7;
            int gm  = m0 + row;
            float4 v = (gm < M)
                ? *reinterpret_cast<const float4*>(&A[(size_t)gm*lda + k0 + c4*4])
                : make_float4(0.f, 0.f, 0.f, 0.f);
            *reinterpret_cast<float4*>(&As[row][c4*4]) = v;
        }
        // load B tile 32x64 (2 float4 / thread)
#pragma unroll
        for (int i = 0; i < 2; i++) {
            int idx = tid + i*256;       // 0..511
            int row = idx >> 4, c4 = idx & 15;
            float4 v = *reinterpret_cast<const float4*>(
                &Bm[(size_t)(k0+row)*ldb + n0 + c4*4]);
            *reinterpret_cast<float4*>(&Bs[row][c4*4]) = v;
        }
        __syncthreads();

#pragma unroll
        for (int kk = 0; kk < BKK; kk += 8) {
            uint32_t ah[2][4], al[2][4];
#pragma unroll
            for (int mt = 0; mt < 2; mt++) {
                int r = warpM*32 + mt*16 + g;
                float a0 = As[r  ][kk + c];
                float a1 = As[r+8][kk + c];
                float a2 = As[r  ][kk + c + 4];
                float a3 = As[r+8][kk + c + 4];
                split_tf32(a0, ah[mt][0], al[mt][0]);
                split_tf32(a1, ah[mt][1], al[mt][1]);
                split_tf32(a2, ah[mt][2], al[mt][2]);
                split_tf32(a3, ah[mt][3], al[mt][3]);
            }
            uint32_t bh[4][2], bl[4][2];
#pragma unroll
            for (int nt = 0; nt < 4; nt++) {
                int ncol = warpN*32 + nt*8 + g;
                float b0 = Bs[kk + c    ][ncol];
                float b1 = Bs[kk + c + 4][ncol];
                split_tf32(b0, bh[nt][0], bl[nt][0]);
                split_tf32(b1, bh[nt][1], bl[nt][1]);
            }
#pragma unroll
            for (int mt = 0; mt < 2; mt++)
#pragma unroll
                for (int nt = 0; nt < 4; nt++) {
                    mma_tf32(acc[mt][nt], ah[mt], bl[nt]);
                    mma_tf32(acc[mt][nt], al[mt], bh[nt]);
                    mma_tf32(acc[mt][nt], ah[mt], bh[nt]);
                }
        }
        __syncthreads();
    }

    // epilogue
#pragma unroll
    for (int mt = 0; mt < 2; mt++) {
#pragma unroll
        for (int nt = 0; nt < 4; nt++) {
            int r0  = m0 + warpM*32 + mt*16 + g;
            int col = n0 + warpN*32 + nt*8 + 2*c;
#pragma unroll
            for (int half = 0; half < 2; half++) {
                int gm = r0 + half*8;
                if (gm >= M) continue;
#pragma unroll
                for (int jj = 0; jj < 2; jj++) {
                    int gn = col + jj;
                    float v = acc[mt][nt][half*2 + jj] + bias[gn];
                    float* cp = &C[(size_t)gm*ldc + gn];
                    if (EPI == 1) v = 0.5f*v*(1.f + erff(v*0.70710678118654752f));
                    if (EPI == 2) v += *cp;
                    *cp = v;
                }
            }
        }
    }
}

template<int EPI>
__global__ __launch_bounds__(256) void mma_gemm_kernel(
    const float* __restrict__ A, int lda,
    const float* __restrict__ Bm, int ldb,
    const float* __restrict__ bias,
    float* __restrict__ C, int ldc, int M, int K)
{
    mma_gemm_tile<EPI>(A, lda, Bm, ldb, bias, C, ldc, M, K,
                       blockIdx.y*BM, blockIdx.x*BN);
}

// per-head QKV via the same MMA tile. grid: (1, Mtiles128, 36 = 12 heads x 3)
__global__ __launch_bounds__(256) void qkv_mma_kernel(
    const float* __restrict__ Wq, const float* __restrict__ bq,
    const float* __restrict__ Wk, const float* __restrict__ bk,
    const float* __restrict__ Wv, const float* __restrict__ bv,
    int layer)
{
    int z = blockIdx.z;
    int h = z % NHD, t = z / NHD;
    const float* W; const float* bi; float* C;
    if (t == 0)      { W = Wq; bi = bq; C = g_Q; }
    else if (t == 1) { W = Wk; bi = bk; C = g_K; }
    else             { W = Wv; bi = bv; C = g_V; }
    size_t off = (size_t)layer*NHD + h;
    mma_gemm_tile<0>(g_H + h*HD, DIM,
                     W + off*HD*HD, HD,
                     bi + off*HD,
                     C + h*HD, DIM,
                     NTOK, HD, blockIdx.y*BM, 0);
}

// -------------------- layernorm ------------------------------------------
__global__ __launch_bounds__(256) void ln_kernel(
    const float* __restrict__ X, float* __restrict__ H,
    const float* __restrict__ gw, const float* __restrict__ bw)
{
    __shared__ float rs[8], rq[8];
    int row = blockIdx.x, tid = threadIdx.x;
    int lane = tid & 31, wid = tid >> 5;
    const float* x = X + (size_t)row*DIM;
    float v0 = x[tid], v1 = x[tid+256], v2 = x[tid+512];
    float s = v0+v1+v2;
    float q = v0*v0 + v1*v1 + v2*v2;
#pragma unroll
    for (int o = 16; o; o >>= 1) {
        s += __shfl_xor_sync(0xffffffffu, s, o);
        q += __shfl_xor_sync(0xffffffffu, q, o);
    }
    if (lane == 0) { rs[wid] = s; rq[wid] = q; }
    __syncthreads();
    if (tid == 0) {
        float ts = 0.f, tq = 0.f;
        for (int w = 0; w < 8; w++) { ts += rs[w]; tq += rq[w]; }
        rs[0] = ts; rq[0] = tq;
    }
    __syncthreads();
    float mean = rs[0]*(1.0f/DIM);
    float var  = rq[0]*(1.0f/DIM) - mean*mean;
    float inv  = rsqrtf(var + 1e-5f);
    float* hrow = H + (size_t)row*DIM;
    hrow[tid]     = (v0-mean)*inv*gw[tid]     + bw[tid];
    hrow[tid+256] = (v1-mean)*inv*gw[tid+256] + bw[tid+256];
    hrow[tid+512] = (v2-mean)*inv*gw[tid+512] + bw[tid+512];
}

// -------------------- attention (one block per (b,h)) --------------------
#define ATTN_SMEM_FLOATS (2*SEQ*HD + HD + SEQ + 8)
#define ATTN_SMEM_BYTES  (ATTN_SMEM_FLOATS*4)

__global__ __launch_bounds__(128) void attn_kernel(
    const float* __restrict__ Q, const float* __restrict__ K,
    const float* __restrict__ V, float* __restrict__ X)
{
    extern __shared__ float sm[];
    float* Ks  = sm;
    float* Vs  = Ks + SEQ*HD;
    float* qs  = Vs + SEQ*HD;
    float* ps  = qs + HD;
    float* red = ps + SEQ;

    int bh = blockIdx.x;
    int b = bh / NHD, h = bh % NHD;
    int tid = threadIdx.x;
    int lane = tid & 31, wid = tid >> 5;
    size_t base = (size_t)b*SEQ*DIM + (size_t)h*HD;

    for (int idx = tid; idx < SEQ*HD; idx += 128) {
        int t = idx >> 6, e = idx & 63;
        Ks[idx] = K[base + (size_t)t*DIM + e];
        Vs[idx] = V[base + (size_t)t*DIM + e];
    }
    __syncthreads();

    int rot = tid & 63;
    for (int s = 0; s < SEQ; s++) {
        if (tid < HD) qs[tid] = Q[base + (size_t)s*DIM + tid];
        __syncthreads();

        float lm = -1e30f;
        for (int j = tid; j < SEQ; j += 128) {
            float d = 0.f;
            const float* kr = &Ks[j*HD];
#pragma unroll
            for (int e = 0; e < HD; e++) {
                int ee = (e + rot) & 63;
                d = fmaf(qs[ee], kr[ee], d);
            }
            d *= 0.125f;
            ps[j] = d;
            lm = fmaxf(lm, d);
        }
#pragma unroll
        for (int o = 16; o; o >>= 1) lm = fmaxf(lm, __shfl_xor_sync(0xffffffffu, lm, o));
        if (lane == 0) red[wid] = lm;
        __syncthreads();
        if (tid == 0) {
            float m = fmaxf(fmaxf(red[0], red[1]), fmaxf(red[2], red[3]));
            red[4] = m;
        }
        __syncthreads();
        float mx = red[4];

        float ls = 0.f;
        for (int j = tid; j < SEQ; j += 128) {
            float e = expf(ps[j] - mx);
            ps[j] = e;
            ls += e;
        }
#pragma unroll
        for (int o = 16; o; o >>= 1) ls += __shfl_xor_sync(0xffffffffu, ls, o);
        __syncthreads();
        if (lane == 0) red[wid] = ls;
        __syncthreads();
        if (tid == 0) red[5] = red[0] + red[1] + red[2] + red[3];
        __syncthreads();
        float inv = 1.f / red[5];

        if (tid < HD) {
            float acc = 0.f;
            for (int t = 0; t < SEQ; t++)
                acc = fmaf(ps[t], Vs[t*HD + tid], acc);
            X[base + (size_t)s*DIM + tid] += acc * inv;
        }
        __syncthreads();
    }
}

// -------------------- classifier head + softmax --------------------------
__global__ __launch_bounds__(256) void head_kernel(
    const float* __restrict__ X, const float* __restrict__ Wh,
    const float* __restrict__ bh, float* __restrict__ out)
{
    __shared__ float xr[DIM];
    __shared__ float lg[NCLS];
    __shared__ float red[8];
    int b = blockIdx.x, tid = threadIdx.x;
    int lane = tid & 31, wid = tid >> 5;

    for (int d = tid; d < DIM; d += 256) xr[d] = X[(size_t)b*SEQ*DIM + d];
    __syncthreads();

    for (int n = tid; n < NCLS; n += 256) {
        float a = bh[n];
        for (int k = 0; k < DIM; k++)
            a = fmaf(xr[k], Wh[(size_t)k*NCLS + n], a);
        lg[n] = a;
    }
    __syncthreads();

    float lm = -1e30f;
    for (int n = tid; n < NCLS; n += 256) lm = fmaxf(lm, lg[n]);
#pragma unroll
    for (int o = 16; o; o >>= 1) lm = fmaxf(lm, __shfl_xor_sync(0xffffffffu, lm, o));
    if (lane == 0) red[wid] = lm;
    __syncthreads();
    if (tid == 0) {
        float m = red[0];
        for (int w = 1; w < 8; w++) m = fmaxf(m, red[w]);
        red[0] = m;
    }
    __syncthreads();
    float mx = red[0];

    float ls = 0.f;
    for (int n = tid; n < NCLS; n += 256) {
        float e = expf(lg[n] - mx);
        lg[n] = e;
        ls += e;
    }
#pragma unroll
    for (int o = 16; o; o >>= 1) ls += __shfl_xor_sync(0xffffffffu, ls, o);
    __syncthreads();
    if (lane == 0) red[wid] = ls;
    __syncthreads();
    if (tid == 0) {
        float s2 = 0.f;
        for (int w = 0; w < 8; w++) s2 += red[w];
        red[0] = s2;
    }
    __syncthreads();
    float inv = 1.f / red[0];
    for (int n = tid; n < NCLS; n += 256)
        out[(size_t)b*NCLS + n] = lg[n]*inv;
}

// -------------------- launch ---------------------------------------------
extern "C" void kernel_launch(void* const* d_in, const int* in_sizes, int n_in,
                              void* d_out, int out_size)
{
    (void)in_sizes; (void)n_in; (void)out_size;
    const float* images = (const float*)d_in[0];
    const float* Wp     = (const float*)d_in[1];
    const float* bp     = (const float*)d_in[2];
    const float* cls    = (const float*)d_in[3];
    const float* pos    = (const float*)d_in[4];
    const float* ln1_g  = (const float*)d_in[5];
    const float* ln1_b  = (const float*)d_in[6];
    const float* Wq     = (const float*)d_in[7];
    const float* bq     = (const float*)d_in[8];
    const float* Wk     = (const float*)d_in[9];
    const float* bk     = (const float*)d_in[10];
    const float* Wv     = (const float*)d_in[11];
    const float* bv     = (const float*)d_in[12];
    const float* ln2_g  = (const float*)d_in[13];
    const float* ln2_b  = (const float*)d_in[14];
    const float* W1     = (const float*)d_in[15];
    const float* b1     = (const float*)d_in[16];
    const float* W2     = (const float*)d_in[17];
    const float* b2     = (const float*)d_in[18];
    const float* Wh     = (const float*)d_in[19];
    const float* bh     = (const float*)d_in[20];
    float* out = (float*)d_out;

    float *pA, *pH, *pX, *pQ, *pK, *pV, *pU;
    cudaGetSymbolAddress((void**)&pA, g_A);
    cudaGetSymbolAddress((void**)&pH, g_H);
    cudaGetSymbolAddress((void**)&pX, g_X);
    cudaGetSymbolAddress((void**)&pQ, g_Q);
    cudaGetSymbolAddress((void**)&pK, g_K);
    cudaGetSymbolAddress((void**)&pV, g_V);
    cudaGetSymbolAddress((void**)&pU, g_U);

    cudaFuncSetAttribute(attn_kernel,
                         cudaFuncAttributeMaxDynamicSharedMemorySize,
                         ATTN_SMEM_BYTES);

    // Patch embed: (6272 x 768) @ (768 x 768)
    patchify_kernel<<<(BB*NPAT*DIM + 255)/256, 256>>>(images);
    mma_gemm_kernel<0><<<dim3(DIM/BN, (BB*NPAT+BM-1)/BM), 256>>>(
        pA, DIM, Wp, DIM, bp, pH, DIM, BB*NPAT, DIM);
    assemble_kernel<<<(NTOK*DIM + 255)/256, 256>>>(cls, pos);

    for (int l = 0; l < NL; l++) {
        ln_kernel<<<NTOK, 256>>>(pX, pH, ln1_g + l*DIM, ln1_b + l*DIM);
        qkv_mma_kernel<<<dim3(1, MT128, NHD*3), 256>>>(Wq, bq, Wk, bk, Wv, bv, l);
        attn_kernel<<<BB*NHD, 128, ATTN_SMEM_BYTES>>>(pQ, pK, pV, pX);
        ln_kernel<<<NTOK, 256>>>(pX, pH, ln2_g + l*DIM, ln2_b + l*DIM);
        mma_gemm_kernel<1><<<dim3(MLPD/BN, MT128), 256>>>(
            pH, DIM, W1 + (size_t)l*DIM*MLPD, MLPD, b1 + (size_t)l*MLPD,
            pU, MLPD, NTOK, DIM);
        mma_gemm_kernel<2><<<dim3(DIM/BN, MT128), 256>>>(
            pU, MLPD, W2 + (size_t)l*MLPD*DIM, DIM, b2 + (size_t)l*DIM,
            pX, DIM, NTOK, MLPD);
    }

    head_kernel<<<BB, 256>>>(pX, Wh, bh, out);
}

// round 5
// speedup vs baseline: 1.3628x; 1.0014x over previous
#include <cuda_runtime.h>
#include <math.h>
#include <stdint.h>

#define BB   32
#define SEQ  197
#define DIM  768
#define NHD  12
#define HD   64
#define NL   12
#define NCLS 1000
#define MLPD 3072
#define NTOK (BB*SEQ)     // 6304
#define NPAT 196
#define MT128 ((NTOK+127)/128)   // 50 M-tiles of 128

// -------------------- scratch (device globals; no allocation allowed) -----
__device__ float g_X[NTOK*DIM];
__device__ float g_H[NTOK*DIM];
__device__ float g_A[BB*NPAT*DIM];
__device__ float g_Q[NTOK*DIM];
__device__ float g_K[NTOK*DIM];
__device__ float g_V[NTOK*DIM];
__device__ float g_U[(size_t)NTOK*MLPD];

// -------------------- patchify: (B,C,224,224) -> (B*196, 768) ------------
__global__ void patchify_kernel(const float* __restrict__ img)
{
    int idx = blockIdx.x*256 + threadIdx.x;
    const int total = BB*NPAT*DIM;
    if (idx >= total) return;
    int f = idx % DIM;
    int p = (idx / DIM) % NPAT;
    int b = idx / (DIM*NPAT);
    int c = f >> 8;
    int rem = f & 255;
    int i = rem >> 4;
    int j = rem & 15;
    int pr = p / 14, pc = p % 14;
    g_A[idx] = img[(((size_t)b*3 + c)*224 + (pr*16+i))*224 + (pc*16+j)];
}

// -------------------- assemble tokens: cls + embed + pos -> X ------------
__global__ void assemble_kernel(const float* __restrict__ cls,
                                const float* __restrict__ pos)
{
    int idx = blockIdx.x*256 + threadIdx.x;
    if (idx >= NTOK*DIM) return;
    int d = idx % DIM;
    int s = (idx / DIM) % SEQ;
    int b = idx / (DIM*SEQ);
    float v = (s == 0) ? cls[d] : g_H[((size_t)b*NPAT + (s-1))*DIM + d];
    g_X[idx] = v + pos[s*DIM + d];
}

// ==================== TF32x3 tensor-core GEMM =============================
// C-tile 128x64 per block, 256 threads (8 warps in 4x2), warp tile 32x32.
// A: MxK row-major (lda), B: KxN row-major (ldb).
// Precision: split each operand into tf32 hi + tf32 lo, do hi*hi+hi*lo+lo*hi.
// EPI 0: C = acc + bias ; 1: C = gelu(acc+bias) ; 2: C += acc + bias

#define BM 128
#define BN 64
#define BKK 32

__device__ __forceinline__ void split_tf32(float x, uint32_t& hi, uint32_t& lo)
{
    uint32_t h;
    asm("cvt.rna.tf32.f32 %0, %1;" : "=r"(h) : "f"(x));
    float r = x - __uint_as_float(h);
    uint32_t l;
    asm("cvt.rna.tf32.f32 %0, %1;" : "=r"(l) : "f"(r));
    hi = h; lo = l;
}

__device__ __forceinline__ void mma_tf32(float* cc, const uint32_t* a, const uint32_t* b)
{
    asm volatile(
        "mma.sync.aligned.m16n8k8.row.col.f32.tf32.tf32.f32 "
        "{%0,%1,%2,%3}, {%4,%5,%6,%7}, {%8,%9}, {%0,%1,%2,%3};\n"
        : "+f"(cc[0]), "+f"(cc[1]), "+f"(cc[2]), "+f"(cc[3])
        : "r"(a[0]), "r"(a[1]), "r"(a[2]), "r"(a[3]),
          "r"(b[0]), "r"(b[1]));
}

template<int EPI>
__device__ __forceinline__ void mma_gemm_tile(
    const float* __restrict__ A, int lda,
    const float* __restrict__ Bm, int ldb,
    const float* __restrict__ bias,
    float* __restrict__ C, int ldc,
    int M, int K, int m0, int n0)
{
    __shared__ float As[BM][BKK+4];   // stride 36: frag reads conflict-free
    __shared__ float Bs[BKK][BN+8];   // stride 72: frag reads conflict-free

    int tid  = threadIdx.x;
    int lane = tid & 31, wid = tid >> 5;
    int warpM = wid >> 1, warpN = wid & 1;
    int g = lane >> 2, c = lane & 3;

    float acc[2][4][4];
#pragma unroll
    for (int mt = 0; mt < 2; mt++)
#pragma unroll
        for (int nt = 0; nt < 4; nt++)
#pragma unroll
            for (int i = 0; i < 4; i++) acc[mt][nt][i] = 0.f;

    for (int k0 = 0; k0 < K; k0 += BKK) {
        // load A tile 128x32 (4 float4 / thread)
#pragma unroll
        for (int i = 0; i < 4; i++) {
            int idx = tid + i*256;       // 0..1023
            int row = idx >> 3, c4 = idx & 7;
            int gm  = m0 + row;
            float4 v = (gm < M)
                ? *reinterpret_cast<const float4*>(&A[(size_t)gm*lda + k0 + c4*4])
                : make_float4(0.f, 0.f, 0.f, 0.f);
            *reinterpret_cast<float4*>(&As[row][c4*4]) = v;
        }
        // load B tile 32x64 (2 float4 / thread)
#pragma unroll
        for (int i = 0; i < 2; i++) {
            int idx = tid + i*256;       // 0..511
            int row = idx >> 4, c4 = idx & 15;
            float4 v = *reinterpret_cast<const float4*>(
                &Bm[(size_t)(k0+row)*ldb + n0 + c4*4]);
            *reinterpret_cast<float4*>(&Bs[row][c4*4]) = v;
        }
        __syncthreads();

#pragma unroll
        for (int kk = 0; kk < BKK; kk += 8) {
            uint32_t ah[2][4], al[2][4];
#pragma unroll
            for (int mt = 0; mt < 2; mt++) {
                int r = warpM*32 + mt*16 + g;
                float a0 = As[r  ][kk + c];
                float a1 = As[r+8][kk + c];
                float a2 = As[r  ][kk + c + 4];
                float a3 = As[r+8][kk + c + 4];
                split_tf32(a0, ah[mt][0], al[mt][0]);
                split_tf32(a1, ah[mt][1], al[mt][1]);
                split_tf32(a2, ah[mt][2], al[mt][2]);
                split_tf32(a3, ah[mt][3], al[mt][3]);
            }
            uint32_t bh[4][2], bl[4][2];
#pragma unroll
            for (int nt = 0; nt < 4; nt++) {
                int ncol = warpN*32 + nt*8 + g;
                float b0 = Bs[kk + c    ][ncol];
                float b1 = Bs[kk + c + 4][ncol];
                split_tf32(b0, bh[nt][0], bl[nt][0]);
                split_tf32(b1, bh[nt][1], bl[nt][1]);
            }
#pragma unroll
            for (int mt = 0; mt < 2; mt++)
#pragma unroll
                for (int nt = 0; nt < 4; nt++) {
                    mma_tf32(acc[mt][nt], ah[mt], bl[nt]);
                    mma_tf32(acc[mt][nt], al[mt], bh[nt]);
                    mma_tf32(acc[mt][nt], ah[mt], bh[nt]);
                }
        }
        __syncthreads();
    }

    // epilogue
#pragma unroll
    for (int mt = 0; mt < 2; mt++) {
#pragma unroll
        for (int nt = 0; nt < 4; nt++) {
            int r0  = m0 + warpM*32 + mt*16 + g;
            int col = n0 + warpN*32 + nt*8 + 2*c;
#pragma unroll
            for (int half = 0; half < 2; half++) {
                int gm = r0 + half*8;
                if (gm >= M) continue;
#pragma unroll
                for (int jj = 0; jj < 2; jj++) {
                    int gn = col + jj;
                    float v = acc[mt][nt][half*2 + jj] + bias[gn];
                    float* cp = &C[(size_t)gm*ldc + gn];
                    if (EPI == 1) v = 0.5f*v*(1.f + erff(v*0.70710678118654752f));
                    if (EPI == 2) v += *cp;
                    *cp = v;
                }
            }
        }
    }
}

template<int EPI>
__global__ __launch_bounds__(256) void mma_gemm_kernel(
    const float* __restrict__ A, int lda,
    const float* __restrict__ Bm, int ldb,
    const float* __restrict__ bias,
    float* __restrict__ C, int ldc, int M, int K)
{
    mma_gemm_tile<EPI>(A, lda, Bm, ldb, bias, C, ldc, M, K,
                       blockIdx.y*BM, blockIdx.x*BN);
}

// per-head QKV via the same MMA tile. grid: (1, Mtiles128, 36 = 12 heads x 3)
__global__ __launch_bounds__(256) void qkv_mma_kernel(
    const float* __restrict__ Wq, const float* __restrict__ bq,
    const float* __restrict__ Wk, const float* __restrict__ bk,
    const float* __restrict__ Wv, const float* __restrict__ bv,
    int layer)
{
    int z = blockIdx.z;
    int h = z % NHD, t = z / NHD;
    const float* W; const float* bi; float* C;
    if (t == 0)      { W = Wq; bi = bq; C = g_Q; }
    else if (t == 1) { W = Wk; bi = bk; C = g_K; }
    else             { W = Wv; bi = bv; C = g_V; }
    size_t off = (size_t)layer*NHD + h;
    mma_gemm_tile<0>(g_H + h*HD, DIM,
                     W + off*HD*HD, HD,
                     bi + off*HD,
                     C + h*HD, DIM,
                     NTOK, HD, blockIdx.y*BM, 0);
}

// -------------------- layernorm ------------------------------------------
__global__ __launch_bounds__(256) void ln_kernel(
    const float* __restrict__ X, float* __restrict__ H,
    const float* __restrict__ gw, const float* __restrict__ bw)
{
    __shared__ float rs[8], rq[8];
    int row = blockIdx.x, tid = threadIdx.x;
    int lane = tid & 31, wid = tid >> 5;
    const float* x = X + (size_t)row*DIM;
    float v0 = x[tid], v1 = x[tid+256], v2 = x[tid+512];
    float s = v0+v1+v2;
    float q = v0*v0 + v1*v1 + v2*v2;
#pragma unroll
    for (int o = 16; o; o >>= 1) {
        s += __shfl_xor_sync(0xffffffffu, s, o);
        q += __shfl_xor_sync(0xffffffffu, q, o);
    }
    if (lane == 0) { rs[wid] = s; rq[wid] = q; }
    __syncthreads();
    if (tid == 0) {
        float ts = 0.f, tq = 0.f;
        for (int w = 0; w < 8; w++) { ts += rs[w]; tq += rq[w]; }
        rs[0] = ts; rq[0] = tq;
    }
    __syncthreads();
    float mean = rs[0]*(1.0f/DIM);
    float var  = rq[0]*(1.0f/DIM) - mean*mean;
    float inv  = rsqrtf(var + 1e-5f);
    float* hrow = H + (size_t)row*DIM;
    hrow[tid]     = (v0-mean)*inv*gw[tid]     + bw[tid];
    hrow[tid+256] = (v1-mean)*inv*gw[tid+256] + bw[tid+256];
    hrow[tid+512] = (v2-mean)*inv*gw[tid+512] + bw[tid+512];
}

// -------------------- attention (one block per (b,h)) --------------------
#define ATTN_SMEM_FLOATS (2*SEQ*HD + HD + SEQ + 8)
#define ATTN_SMEM_BYTES  (ATTN_SMEM_FLOATS*4)

__global__ __launch_bounds__(128) void attn_kernel(
    const float* __restrict__ Q, const float* __restrict__ K,
    const float* __restrict__ V, float* __restrict__ X)
{
    extern __shared__ float sm[];
    float* Ks  = sm;
    float* Vs  = Ks + SEQ*HD;
    float* qs  = Vs + SEQ*HD;
    float* ps  = qs + HD;
    float* red = ps + SEQ;

    int bh = blockIdx.x;
    int b = bh / NHD, h = bh % NHD;
    int tid = threadIdx.x;
    int lane = tid & 31, wid = tid >> 5;
    size_t base = (size_t)b*SEQ*DIM + (size_t)h*HD;

    for (int idx = tid; idx < SEQ*HD; idx += 128) {
        int t = idx >> 6, e = idx & 63;
        Ks[idx] = K[base + (size_t)t*DIM + e];
        Vs[idx] = V[base + (size_t)t*DIM + e];
    }
    __syncthreads();

    int rot = tid & 63;
    for (int s = 0; s < SEQ; s++) {
        if (tid < HD) qs[tid] = Q[base + (size_t)s*DIM + tid];
        __syncthreads();

        float lm = -1e30f;
        for (int j = tid; j < SEQ; j += 128) {
            float d = 0.f;
            const float* kr = &Ks[j*HD];
#pragma unroll
            for (int e = 0; e < HD; e++) {
                int ee = (e + rot) & 63;
                d = fmaf(qs[ee], kr[ee], d);
            }
            d *= 0.125f;
            ps[j] = d;
            lm = fmaxf(lm, d);
        }
#pragma unroll
        for (int o = 16; o; o >>= 1) lm = fmaxf(lm, __shfl_xor_sync(0xffffffffu, lm, o));
        if (lane == 0) red[wid] = lm;
        __syncthreads();
        if (tid == 0) {
            float m = fmaxf(fmaxf(red[0], red[1]), fmaxf(red[2], red[3]));
            red[4] = m;
        }
        __syncthreads();
        float mx = red[4];

        float ls = 0.f;
        for (int j = tid; j < SEQ; j += 128) {
            float e = expf(ps[j] - mx);
            ps[j] = e;
            ls += e;
        }
#pragma unroll
        for (int o = 16; o; o >>= 1) ls += __shfl_xor_sync(0xffffffffu, ls, o);
        __syncthreads();
        if (lane == 0) red[wid] = ls;
        __syncthreads();
        if (tid == 0) red[5] = red[0] + red[1] + red[2] + red[3];
        __syncthreads();
        float inv = 1.f / red[5];

        if (tid < HD) {
            float acc = 0.f;
            for (int t = 0; t < SEQ; t++)
                acc = fmaf(ps[t], Vs[t*HD + tid], acc);
            X[base + (size_t)s*DIM + tid] += acc * inv;
        }
        __syncthreads();
    }
}

// -------------------- classifier head + softmax --------------------------
__global__ __launch_bounds__(256) void head_kernel(
    const float* __restrict__ X, const float* __restrict__ Wh,
    const float* __restrict__ bh, float* __restrict__ out)
{
    __shared__ float xr[DIM];
    __shared__ float lg[NCLS];
    __shared__ float red[8];
    int b = blockIdx.x, tid = threadIdx.x;
    int lane = tid & 31, wid = tid >> 5;

    for (int d = tid; d < DIM; d += 256) xr[d] = X[(size_t)b*SEQ*DIM + d];
    __syncthreads();

    for (int n = tid; n < NCLS; n += 256) {
        float a = bh[n];
        for (int k = 0; k < DIM; k++)
            a = fmaf(xr[k], Wh[(size_t)k*NCLS + n], a);
        lg[n] = a;
    }
    __syncthreads();

    float lm = -1e30f;
    for (int n = tid; n < NCLS; n += 256) lm = fmaxf(lm, lg[n]);
#pragma unroll
    for (int o = 16; o; o >>= 1) lm = fmaxf(lm, __shfl_xor_sync(0xffffffffu, lm, o));
    if (lane == 0) red[wid] = lm;
    __syncthreads();
    if (tid == 0) {
        float m = red[0];
        for (int w = 1; w < 8; w++) m = fmaxf(m, red[w]);
        red[0] = m;
    }
    __syncthreads();
    float mx = red[0];

    float ls = 0.f;
    for (int n = tid; n < NCLS; n += 256) {
        float e = expf(lg[n] - mx);
        lg[n] = e;
        ls += e;
    }
#pragma unroll
    for (int o = 16; o; o >>= 1) ls += __shfl_xor_sync(0xffffffffu, ls, o);
    __syncthreads();
    if (lane == 0) red[wid] = ls;
    __syncthreads();
    if (tid == 0) {
        float s2 = 0.f;
        for (int w = 0; w < 8; w++) s2 += red[w];
        red[0] = s2;
    }
    __syncthreads();
    float inv = 1.f / red[0];
    for (int n = tid; n < NCLS; n += 256)
        out[(size_t)b*NCLS + n] = lg[n]*inv;
}

// -------------------- launch ---------------------------------------------
extern "C" void kernel_launch(void* const* d_in, const int* in_sizes, int n_in,
                              void* d_out, int out_size)
{
    (void)in_sizes; (void)n_in; (void)out_size;
    const float* images = (const float*)d_in[0];
    const float* Wp     = (const float*)d_in[1];
    const float* bp     = (const float*)d_in[2];
    const float* cls    = (const float*)d_in[3];
    const float* pos    = (const float*)d_in[4];
    const float* ln1_g  = (const float*)d_in[5];
    const float* ln1_b  = (const float*)d_in[6];
    const float* Wq     = (const float*)d_in[7];
    const float* bq     = (const float*)d_in[8];
    const float* Wk     = (const float*)d_in[9];
    const float* bk     = (const float*)d_in[10];
    const float* Wv     = (const float*)d_in[11];
    const float* bv     = (const float*)d_in[12];
    const float* ln2_g  = (const float*)d_in[13];
    const float* ln2_b  = (const float*)d_in[14];
    const float* W1     = (const float*)d_in[15];
    const float* b1     = (const float*)d_in[16];
    const float* W2     = (const float*)d_in[17];
    const float* b2     = (const float*)d_in[18];
    const float* Wh     = (const float*)d_in[19];
    const float* bh     = (const float*)d_in[20];
    float* out = (float*)d_out;

    float *pA, *pH, *pX, *pQ, *pK, *pV, *pU;
    cudaGetSymbolAddress((void**)&pA, g_A);
    cudaGetSymbolAddress((void**)&pH, g_H);
    cudaGetSymbolAddress((void**)&pX, g_X);
    cudaGetSymbolAddress((void**)&pQ, g_Q);
    cudaGetSymbolAddress((void**)&pK, g_K);
    cudaGetSymbolAddress((void**)&pV, g_V);
    cudaGetSymbolAddress((void**)&pU, g_U);

    cudaFuncSetAttribute(attn_kernel,
                         cudaFuncAttributeMaxDynamicSharedMemorySize,
                         ATTN_SMEM_BYTES);

    // Patch embed: (6272 x 768) @ (768 x 768)
    patchify_kernel<<<(BB*NPAT*DIM + 255)/256, 256>>>(images);
    mma_gemm_kernel<0><<<dim3(DIM/BN, (BB*NPAT+BM-1)/BM), 256>>>(
        pA, DIM, Wp, DIM, bp, pH, DIM, BB*NPAT, DIM);
    assemble_kernel<<<(NTOK*DIM + 255)/256, 256>>>(cls, pos);

    for (int l = 0; l < NL; l++) {
        ln_kernel<<<NTOK, 256>>>(pX, pH, ln1_g + l*DIM, ln1_b + l*DIM);
        qkv_mma_kernel<<<dim3(1, MT128, NHD*3), 256>>>(Wq, bq, Wk, bk, Wv, bv, l);
        attn_kernel<<<BB*NHD, 128, ATTN_SMEM_BYTES>>>(pQ, pK, pV, pX);
        ln_kernel<<<NTOK, 256>>>(pX, pH, ln2_g + l*DIM, ln2_b + l*DIM);
        mma_gemm_kernel<1><<<dim3(MLPD/BN, MT128), 256>>>(
            pH, DIM, W1 + (size_t)l*DIM*MLPD, MLPD, b1 + (size_t)l*MLPD,
            pU, MLPD, NTOK, DIM);
        mma_gemm_kernel<2><<<dim3(DIM/BN, MT128), 256>>>(
            pU, MLPD, W2 + (size_t)l*MLPD*DIM, DIM, b2 + (size_t)l*DIM,
            pX, DIM, NTOK, MLPD);
    }

    head_kernel<<<BB, 256>>>(pX, Wh, bh, out);
}

// round 6
// speedup vs baseline: 1.3663x; 1.0026x over previous
#include <cuda_runtime.h>
#include <math.h>
#include <stdint.h>

#define BB   32
#define SEQ  197
#define DIM  768
#define NHD  12
#define HD   64
#define NL   12
#define NCLS 1000
#define MLPD 3072
#define NTOK (BB*SEQ)     // 6304
#define NPAT 196
#define MT128 ((NTOK+127)/128)   // 50 M-tiles of 128

// -------------------- scratch (device globals; no allocation allowed) -----
__device__ float g_X[NTOK*DIM];
__device__ float g_H[NTOK*DIM];
__device__ float g_A[BB*NPAT*DIM];
__device__ float g_Q[NTOK*DIM];
__device__ float g_K[NTOK*DIM];
__device__ float g_V[NTOK*DIM];
__device__ float g_U[(size_t)NTOK*MLPD];

// -------------------- patchify: (B,C,224,224) -> (B*196, 768) ------------
__global__ void patchify_kernel(const float* __restrict__ img)
{
    int idx = blockIdx.x*256 + threadIdx.x;
    const int total = BB*NPAT*DIM;
    if (idx >= total) return;
    int f = idx % DIM;
    int p = (idx / DIM) % NPAT;
    int b = idx / (DIM*NPAT);
    int c = f >> 8;
    int rem = f & 255;
    int i = rem >> 4;
    int j = rem & 15;
    int pr = p / 14, pc = p % 14;
    g_A[idx] = img[(((size_t)b*3 + c)*224 + (pr*16+i))*224 + (pc*16+j)];
}

// -------------------- assemble tokens: cls + embed + pos -> X ------------
__global__ void assemble_kernel(const float* __restrict__ cls,
                                const float* __restrict__ pos)
{
    int idx = blockIdx.x*256 + threadIdx.x;
    if (idx >= NTOK*DIM) return;
    int d = idx % DIM;
    int s = (idx / DIM) % SEQ;
    int b = idx / (DIM*SEQ);
    float v = (s == 0) ? cls[d] : g_H[((size_t)b*NPAT + (s-1))*DIM + d];
    g_X[idx] = v + pos[s*DIM + d];
}

// ==================== TF32x3 tensor-core GEMM =============================
// C-tile 128x64 per block, 256 threads (8 warps in 4x2), warp tile 32x32.
// A: MxK row-major (lda), B: KxN row-major (ldb).
// Precision: split each operand into tf32 hi + tf32 lo, do hi*hi+hi*lo+lo*hi.
// EPI 0: C = acc + bias ; 1: C = gelu(acc+bias) ; 2: C += acc + bias

#define BM 128
#define BN 64
#define BKK 32

__device__ __forceinline__ void split_tf32(float x, uint32_t& hi, uint32_t& lo)
{
    uint32_t h;
    asm("cvt.rna.tf32.f32 %0, %1;" : "=r"(h) : "f"(x));
    float r = x - __uint_as_float(h);
    uint32_t l;
    asm("cvt.rna.tf32.f32 %0, %1;" : "=r"(l) : "f"(r));
    hi = h; lo = l;
}

__device__ __forceinline__ void mma_tf32(float* cc, const uint32_t* a, const uint32_t* b)
{
    asm volatile(
        "mma.sync.aligned.m16n8k8.row.col.f32.tf32.tf32.f32 "
        "{%0,%1,%2,%3}, {%4,%5,%6,%7}, {%8,%9}, {%0,%1,%2,%3};\n"
        : "+f"(cc[0]), "+f"(cc[1]), "+f"(cc[2]), "+f"(cc[3])
        : "r"(a[0]), "r"(a[1]), "r"(a[2]), "r"(a[3]),
          "r"(b[0]), "r"(b[1]));
}

template<int EPI>
__device__ __forceinline__ void mma_gemm_tile(
    const float* __restrict__ A, int lda,
    const float* __restrict__ Bm, int ldb,
    const float* __restrict__ bias,
    float* __restrict__ C, int ldc,
    int M, int K, int m0, int n0)
{
    __shared__ float As[BM][BKK+4];   // stride 36: frag reads conflict-free
    __shared__ float Bs[BKK][BN+8];   // stride 72: frag reads conflict-free

    int tid  = threadIdx.x;
    int lane = tid & 31, wid = tid >> 5;
    int warpM = wid >> 1, warpN = wid & 1;
    int g = lane >> 2, c = lane & 3;

    float acc[2][4][4];
#pragma unroll
    for (int mt = 0; mt < 2; mt++)
#pragma unroll
        for (int nt = 0; nt < 4; nt++)
#pragma unroll
            for (int i = 0; i < 4; i++) acc[mt][nt][i] = 0.f;

    for (int k0 = 0; k0 < K; k0 += BKK) {
        // load A tile 128x32 (4 float4 / thread)
#pragma unroll
        for (int i = 0; i < 4; i++) {
            int idx = tid + i*256;       // 0..1023
            int row = idx >> 3, c4 = idx & 7;
            int gm  = m0 + row;
            float4 v = (gm < M)
                ? *reinterpret_cast<const float4*>(&A[(size_t)gm*lda + k0 + c4*4])
                : make_float4(0.f, 0.f, 0.f, 0.f);
            *reinterpret_cast<float4*>(&As[row][c4*4]) = v;
        }
        // load B tile 32x64 (2 float4 / thread)
#pragma unroll
        for (int i = 0; i < 2; i++) {
            int idx = tid + i*256;       // 0..511
            int row = idx >> 4, c4 = idx & 15;
            float4 v = *reinterpret_cast<const float4*>(
                &Bm[(size_t)(k0+row)*ldb + n0 + c4*4]);
            *reinterpret_cast<float4*>(&Bs[row][c4*4]) = v;
        }
        __syncthreads();

#pragma unroll
        for (int kk = 0; kk < BKK; kk += 8) {
            uint32_t ah[2][4], al[2][4];
#pragma unroll
            for (int mt = 0; mt < 2; mt++) {
                int r = warpM*32 + mt*16 + g;
                float a0 = As[r  ][kk + c];
                float a1 = As[r+8][kk + c];
                float a2 = As[r  ][kk + c + 4];
                float a3 = As[r+8][kk + c + 4];
                split_tf32(a0, ah[mt][0], al[mt][0]);
                split_tf32(a1, ah[mt][1], al[mt][1]);
                split_tf32(a2, ah[mt][2], al[mt][2]);
                split_tf32(a3, ah[mt][3], al[mt][3]);
            }
            uint32_t bh[4][2], bl[4][2];
#pragma unroll
            for (int nt = 0; nt < 4; nt++) {
                int ncol = warpN*32 + nt*8 + g;
                float b0 = Bs[kk + c    ][ncol];
                float b1 = Bs[kk + c + 4][ncol];
                split_tf32(b0, bh[nt][0], bl[nt][0]);
                split_tf32(b1, bh[nt][1], bl[nt][1]);
            }
#pragma unroll
            for (int mt = 0; mt < 2; mt++)
#pragma unroll
                for (int nt = 0; nt < 4; nt++) {
                    mma_tf32(acc[mt][nt], ah[mt], bl[nt]);
                    mma_tf32(acc[mt][nt], al[mt], bh[nt]);
                    mma_tf32(acc[mt][nt], ah[mt], bh[nt]);
                }
        }
        __syncthreads();
    }

    // epilogue
#pragma unroll
    for (int mt = 0; mt < 2; mt++) {
#pragma unroll
        for (int nt = 0; nt < 4; nt++) {
            int r0  = m0 + warpM*32 + mt*16 + g;
            int col = n0 + warpN*32 + nt*8 + 2*c;
#pragma unroll
            for (int half = 0; half < 2; half++) {
                int gm = r0 + half*8;
                if (gm >= M) continue;
#pragma unroll
                for (int jj = 0; jj < 2; jj++) {
                    int gn = col + jj;
                    float v = acc[mt][nt][half*2 + jj] + bias[gn];
                    float* cp = &C[(size_t)gm*ldc + gn];
                    if (EPI == 1) v = 0.5f*v*(1.f + erff(v*0.70710678118654752f));
                    if (EPI == 2) v += *cp;
                    *cp = v;
                }
            }
        }
    }
}

template<int EPI>
__global__ __launch_bounds__(256) void mma_gemm_kernel(
    const float* __restrict__ A, int lda,
    const float* __restrict__ Bm, int ldb,
    const float* __restrict__ bias,
    float* __restrict__ C, int ldc, int M, int K)
{
    mma_gemm_tile<EPI>(A, lda, Bm, ldb, bias, C, ldc, M, K,
                       blockIdx.y*BM, blockIdx.x*BN);
}

// per-head QKV via the same MMA tile. grid: (1, Mtiles128, 36 = 12 heads x 3)
__global__ __launch_bounds__(256) void qkv_mma_kernel(
    const float* __restrict__ Wq, const float* __restrict__ bq,
    const float* __restrict__ Wk, const float* __restrict__ bk,
    const float* __restrict__ Wv, const float* __restrict__ bv,
    int layer)
{
    int z = blockIdx.z;
    int h = z % NHD, t = z / NHD;
    const float* W; const float* bi; float* C;
    if (t == 0)      { W = Wq; bi = bq; C = g_Q; }
    else if (t == 1) { W = Wk; bi = bk; C = g_K; }
    else             { W = Wv; bi = bv; C = g_V; }
    size_t off = (size_t)layer*NHD + h;
    mma_gemm_tile<0>(g_H + h*HD, DIM,
                     W + off*HD*HD, HD,
                     bi + off*HD,
                     C + h*HD, DIM,
                     NTOK, HD, blockIdx.y*BM, 0);
}

// -------------------- layernorm ------------------------------------------
__global__ __launch_bounds__(256) void ln_kernel(
    const float* __restrict__ X, float* __restrict__ H,
    const float* __restrict__ gw, const float* __restrict__ bw)
{
    __shared__ float rs[8], rq[8];
    int row = blockIdx.x, tid = threadIdx.x;
    int lane = tid & 31, wid = tid >> 5;
    const float* x = X + (size_t)row*DIM;
    float v0 = x[tid], v1 = x[tid+256], v2 = x[tid+512];
    float s = v0+v1+v2;
    float q = v0*v0 + v1*v1 + v2*v2;
#pragma unroll
    for (int o = 16; o; o >>= 1) {
        s += __shfl_xor_sync(0xffffffffu, s, o);
        q += __shfl_xor_sync(0xffffffffu, q, o);
    }
    if (lane == 0) { rs[wid] = s; rq[wid] = q; }
    __syncthreads();
    if (tid == 0) {
        float ts = 0.f, tq = 0.f;
        for (int w = 0; w < 8; w++) { ts += rs[w]; tq += rq[w]; }
        rs[0] = ts; rq[0] = tq;
    }
    __syncthreads();
    float mean = rs[0]*(1.0f/DIM);
    float var  = rq[0]*(1.0f/DIM) - mean*mean;
    float inv  = rsqrtf(var + 1e-5f);
    float* hrow = H + (size_t)row*DIM;
    hrow[tid]     = (v0-mean)*inv*gw[tid]     + bw[tid];
    hrow[tid+256] = (v1-mean)*inv*gw[tid+256] + bw[tid+256];
    hrow[tid+512] = (v2-mean)*inv*gw[tid+512] + bw[tid+512];
}

// -------------------- attention (one block per (b,h)) --------------------
#define ATTN_SMEM_FLOATS (2*SEQ*HD + HD + SEQ + 8)
#define ATTN_SMEM_BYTES  (ATTN_SMEM_FLOATS*4)

__global__ __launch_bounds__(128) void attn_kernel(
    const float* __restrict__ Q, const float* __restrict__ K,
    const float* __restrict__ V, float* __restrict__ X)
{
    extern __shared__ float sm[];
    float* Ks  = sm;
    float* Vs  = Ks + SEQ*HD;
    float* qs  = Vs + SEQ*HD;
    float* ps  = qs + HD;
    float* red = ps + SEQ;

    int bh = blockIdx.x;
    int b = bh / NHD, h = bh % NHD;
    int tid = threadIdx.x;
    int lane = tid & 31, wid = tid >> 5;
    size_t base = (size_t)b*SEQ*DIM + (size_t)h*HD;

    for (int idx = tid; idx < SEQ*HD; idx += 128) {
        int t = idx >> 6, e = idx & 63;
        Ks[idx] = K[base + (size_t)t*DIM + e];
        Vs[idx] = V[base + (size_t)t*DIM + e];
    }
    __syncthreads();

    int rot = tid & 63;
    for (int s = 0; s < SEQ; s++) {
        if (tid < HD) qs[tid] = Q[base + (size_t)s*DIM + tid];
        __syncthreads();

        float lm = -1e30f;
        for (int j = tid; j < SEQ; j += 128) {
            float d = 0.f;
            const float* kr = &Ks[j*HD];
#pragma unroll
            for (int e = 0; e < HD; e++) {
                int ee = (e + rot) & 63;
                d = fmaf(qs[ee], kr[ee], d);
            }
            d *= 0.125f;
            ps[j] = d;
            lm = fmaxf(lm, d);
        }
#pragma unroll
        for (int o = 16; o; o >>= 1) lm = fmaxf(lm, __shfl_xor_sync(0xffffffffu, lm, o));
        if (lane == 0) red[wid] = lm;
        __syncthreads();
        if (tid == 0) {
            float m = fmaxf(fmaxf(red[0], red[1]), fmaxf(red[2], red[3]));
            red[4] = m;
        }
        __syncthreads();
        float mx = red[4];

        float ls = 0.f;
        for (int j = tid; j < SEQ; j += 128) {
            float e = expf(ps[j] - mx);
            ps[j] = e;
            ls += e;
        }
#pragma unroll
        for (int o = 16; o; o >>= 1) ls += __shfl_xor_sync(0xffffffffu, ls, o);
        __syncthreads();
        if (lane == 0) red[wid] = ls;
        __syncthreads();
        if (tid == 0) red[5] = red[0] + red[1] + red[2] + red[3];
        __syncthreads();
        float inv = 1.f / red[5];

        if (tid < HD) {
            float acc = 0.f;
            for (int t = 0; t < SEQ; t++)
                acc = fmaf(ps[t], Vs[t*HD + tid], acc);
            X[base + (size_t)s*DIM + tid] += acc * inv;
        }
        __syncthreads();
    }
}

// -------------------- classifier head + softmax --------------------------
__global__ __launch_bounds__(256) void head_kernel(
    const float* __restrict__ X, const float* __restrict__ Wh,
    const float* __restrict__ bh, float* __restrict__ out)
{
    __shared__ float xr[DIM];
    __shared__ float lg[NCLS];
    __shared__ float red[8];
    int b = blockIdx.x, tid = threadIdx.x;
    int lane = tid & 31, wid = tid >> 5;

    for (int d = tid; d < DIM; d += 256) xr[d] = X[(size_t)b*SEQ*DIM + d];
    __syncthreads();

    for (int n = tid; n < NCLS; n += 256) {
        float a = bh[n];
        for (int k = 0; k < DIM; k++)
            a = fmaf(xr[k], Wh[(size_t)k*NCLS + n], a);
        lg[n] = a;
    }
    __syncthreads();

    float lm = -1e30f;
    for (int n = tid; n < NCLS; n += 256) lm = fmaxf(lm, lg[n]);
#pragma unroll
    for (int o = 16; o; o >>= 1) lm = fmaxf(lm, __shfl_xor_sync(0xffffffffu, lm, o));
    if (lane == 0) red[wid] = lm;
    __syncthreads();
    if (tid == 0) {
        float m = red[0];
        for (int w = 1; w < 8; w++) m = fmaxf(m, red[w]);
        red[0] = m;
    }
    __syncthreads();
    float mx = red[0];

    float ls = 0.f;
    for (int n = tid; n < NCLS; n += 256) {
        float e = expf(lg[n] - mx);
        lg[n] = e;
        ls += e;
    }
#pragma unroll
    for (int o = 16; o; o >>= 1) ls += __shfl_xor_sync(0xffffffffu, ls, o);
    __syncthreads();
    if (lane == 0) red[wid] = ls;
    __syncthreads();
    if (tid == 0) {
        float s2 = 0.f;
        for (int w = 0; w < 8; w++) s2 += red[w];
        red[0] = s2;
    }
    __syncthreads();
    float inv = 1.f / red[0];
    for (int n = tid; n < NCLS; n += 256)
        out[(size_t)b*NCLS + n] = lg[n]*inv;
}

// -------------------- launch ---------------------------------------------
extern "C" void kernel_launch(void* const* d_in, const int* in_sizes, int n_in,
                              void* d_out, int out_size)
{
    (void)in_sizes; (void)n_in; (void)out_size;
    const float* images = (const float*)d_in[0];
    const float* Wp     = (const float*)d_in[1];
    const float* bp     = (const float*)d_in[2];
    const float* cls    = (const float*)d_in[3];
    const float* pos    = (const float*)d_in[4];
    const float* ln1_g  = (const float*)d_in[5];
    const float* ln1_b  = (const float*)d_in[6];
    const float* Wq     = (const float*)d_in[7];
    const float* bq     = (const float*)d_in[8];
    const float* Wk     = (const float*)d_in[9];
    const float* bk     = (const float*)d_in[10];
    const float* Wv     = (const float*)d_in[11];
    const float* bv     = (const float*)d_in[12];
    const float* ln2_g  = (const float*)d_in[13];
    const float* ln2_b  = (const float*)d_in[14];
    const float* W1     = (const float*)d_in[15];
    const float* b1     = (const float*)d_in[16];
    const float* W2     = (const float*)d_in[17];
    const float* b2     = (const float*)d_in[18];
    const float* Wh     = (const float*)d_in[19];
    const float* bh     = (const float*)d_in[20];
    float* out = (float*)d_out;

    float *pA, *pH, *pX, *pQ, *pK, *pV, *pU;
    cudaGetSymbolAddress((void**)&pA, g_A);
    cudaGetSymbolAddress((void**)&pH, g_H);
    cudaGetSymbolAddress((void**)&pX, g_X);
    cudaGetSymbolAddress((void**)&pQ, g_Q);
    cudaGetSymbolAddress((void**)&pK, g_K);
    cudaGetSymbolAddress((void**)&pV, g_V);
    cudaGetSymbolAddress((void**)&pU, g_U);

    cudaFuncSetAttribute(attn_kernel,
                         cudaFuncAttributeMaxDynamicSharedMemorySize,
                         ATTN_SMEM_BYTES);

    // Patch embed: (6272 x 768) @ (768 x 768)
    patchify_kernel<<<(BB*NPAT*DIM + 255)/256, 256>>>(images);
    mma_gemm_kernel<0><<<dim3(DIM/BN, (BB*NPAT+BM-1)/BM), 256>>>(
        pA, DIM, Wp, DIM, bp, pH, DIM, BB*NPAT, DIM);
    assemble_kernel<<<(NTOK*DIM + 255)/256, 256>>>(cls, pos);

    for (int l = 0; l < NL; l++) {
        ln_kernel<<<NTOK, 256>>>(pX, pH, ln1_g + l*DIM, ln1_b + l*DIM);
        qkv_mma_kernel<<<dim3(1, MT128, NHD*3), 256>>>(Wq, bq, Wk, bk, Wv, bv, l);
        attn_kernel<<<BB*NHD, 128, ATTN_SMEM_BYTES>>>(pQ, pK, pV, pX);
        ln_kernel<<<NTOK, 256>>>(pX, pH, ln2_g + l*DIM, ln2_b + l*DIM);
        mma_gemm_kernel<1><<<dim3(MLPD/BN, MT128), 256>>>(
            pH, DIM, W1 + (size_t)l*DIM*MLPD, MLPD, b1 + (size_t)l*MLPD,
            pU, MLPD, NTOK, DIM);
        mma_gemm_kernel<2><<<dim3(DIM/BN, MT128), 256>>>(
            pU, MLPD, W2 + (size_t)l*MLPD*DIM, DIM, b2 + (size_t)l*DIM,
            pX, DIM, NTOK, MLPD);
    }

    head_kernel<<<BB, 256>>>(pX, Wh, bh, out);
}